// round 6
// baseline (speedup 1.0000x reference)
#include <cuda_runtime.h>
#include <cuda_bf16.h>
#include <cstdint>

#define NMAX 100000
#define EMAX 1700000
#define D    128

// ---------------- scratch (__device__ globals) ------------------------------
__device__ __align__(16) float g_P[(size_t)NMAX * D];
__device__ __align__(16) float g_R[(size_t)NMAX * D];
__device__ __align__(16) float g_H[(size_t)NMAX * D];
// weights: [mat 0..3][hi/lo][n 0..127][k padded 136] bf16
#define WSTRIDE 136
#define WMAT (128 * WSTRIDE)
__device__ __align__(16) uint16_t g_Wb[4 * 2 * WMAT];
__device__ int g_cnt[NMAX];
__device__ int g_ptr[NMAX + 1];
__device__ int g_fill[NMAX];
__device__ int g_nbr[EMAX];
__device__ int g_bsum[256];
__device__ int g_boff[256];
__device__ int g_is64;

// ---------------- helpers ----------------------------------------------------
__device__ __forceinline__ uint32_t smem_to_u32(const void* p) {
    uint32_t a;
    asm("{ .reg .u64 t; cvta.to.shared.u64 t, %1; cvt.u32.u64 %0, t; }" : "=r"(a) : "l"(p));
    return a;
}
__device__ __forceinline__ void ldsm_x4(uint32_t addr, uint32_t& r0, uint32_t& r1,
                                        uint32_t& r2, uint32_t& r3) {
    asm volatile("ldmatrix.sync.aligned.m8n8.x4.shared.b16 {%0,%1,%2,%3}, [%4];"
                 : "=r"(r0), "=r"(r1), "=r"(r2), "=r"(r3) : "r"(addr));
}
__device__ __forceinline__ void mma16816(float* d, uint32_t a0, uint32_t a1, uint32_t a2,
                                         uint32_t a3, uint32_t b0, uint32_t b1) {
    asm volatile(
        "mma.sync.aligned.m16n8k16.row.col.f32.bf16.bf16.f32 "
        "{%0,%1,%2,%3}, {%4,%5,%6,%7}, {%8,%9}, {%0,%1,%2,%3};"
        : "+f"(d[0]), "+f"(d[1]), "+f"(d[2]), "+f"(d[3])
        : "r"(a0), "r"(a1), "r"(a2), "r"(a3), "r"(b0), "r"(b1));
}
__device__ __forceinline__ uint32_t pack_bf(float lo, float hi) {
    uint32_t r;
    asm("cvt.rn.bf16x2.f32 %0, %1, %2;" : "=r"(r) : "f"(hi), "f"(lo));
    return r;
}

// ---- edge dtype detect ------------------------------------------------------
__global__ void detect_kernel(const int* __restrict__ ei32, int E) {
    if (threadIdx.x == 0) {
        int m = E < 64 ? E : 64;
        int is64 = 1;
        for (int i = 0; i < m; i++)
            if (ei32[2 * i + 1] != 0) { is64 = 0; break; }
        g_is64 = is64;
    }
}
__device__ __forceinline__ int get_idx(const void* __restrict__ ei, int is64, long long e) {
    if (is64) return (int)((const long long*)ei)[e];
    return ((const int*)ei)[e];
}

// ---- CSR build --------------------------------------------------------------
__global__ void zero_cnt_kernel(int n) {
    for (int i = blockIdx.x * blockDim.x + threadIdx.x; i < n; i += gridDim.x * blockDim.x)
        g_cnt[i] = 0;
}
__global__ void count_kernel(const void* __restrict__ ei, int E) {
    int e = blockIdx.x * blockDim.x + threadIdx.x;
    int is64 = g_is64;
    if (e < E) atomicAdd(&g_cnt[get_idx(ei, is64, (long long)E + e)], 1);
}
__global__ void scanA_kernel(int n) {
    __shared__ int s[512];
    int tid = threadIdx.x;
    int i = blockIdx.x * 512 + tid;
    int x = (i < n) ? g_cnt[i] : 0;
    s[tid] = x;
    __syncthreads();
    for (int off = 1; off < 512; off <<= 1) {
        int v = (tid >= off) ? s[tid - off] : 0;
        __syncthreads();
        s[tid] += v;
        __syncthreads();
    }
    if (i < n) g_ptr[i] = s[tid] - x;
    if (tid == 511) g_bsum[blockIdx.x] = s[tid];
}
__global__ void scanB_kernel(int nb) {
    __shared__ int s[256];
    int tid = threadIdx.x;
    int x = (tid < nb) ? g_bsum[tid] : 0;
    s[tid] = x;
    __syncthreads();
    for (int off = 1; off < 256; off <<= 1) {
        int v = (tid >= off) ? s[tid - off] : 0;
        __syncthreads();
        s[tid] += v;
        __syncthreads();
    }
    if (tid < nb) g_boff[tid] = s[tid] - x;
}
__global__ void scanC_kernel(int n, int E) {
    int i = blockIdx.x * blockDim.x + threadIdx.x;
    if (i < n) {
        int v = g_ptr[i] + g_boff[i >> 9];
        g_ptr[i] = v;
        g_fill[i] = v;
    }
    if (i == 0) g_ptr[n] = E;
}
__global__ void fill_kernel(const void* __restrict__ ei, int E) {
    int e = blockIdx.x * blockDim.x + threadIdx.x;
    int is64 = g_is64;
    if (e < E) {
        int s = get_idx(ei, is64, e);
        int d = get_idx(ei, is64, (long long)E + e);
        int pos = atomicAdd(&g_fill[d], 1);
        g_nbr[pos] = s;
    }
}

// ---------------------------------------------------------------------------
// Weight precompute: W[k][n] fp32 -> B^T[n][k] bf16 hi/lo, padded stride 136
// ---------------------------------------------------------------------------
__global__ void wconv_kernel(const float* __restrict__ W0, const float* __restrict__ W1,
                             const float* __restrict__ W2, const float* __restrict__ W3) {
    int m = blockIdx.x;
    const float* W = (m == 0) ? W0 : (m == 1) ? W1 : (m == 2) ? W2 : W3;
    for (int e = threadIdx.x; e < 16384; e += blockDim.x) {
        int k = e >> 7;
        int nn = e & 127;
        float x = W[k * 128 + nn];
        __nv_bfloat16 hb = __float2bfloat16(x);
        float hf = __bfloat162float(hb);
        __nv_bfloat16 lb = __float2bfloat16(x - hf);
        g_Wb[(m * 2 + 0) * WMAT + nn * WSTRIDE + k] = *(uint16_t*)&hb;
        g_Wb[(m * 2 + 1) * WMAT + nn * WSTRIDE + k] = *(uint16_t*)&lb;
    }
}

// ---------------------------------------------------------------------------
// Dual GEMM via mma.sync bf16 (hi/lo split, 3 products):
//   P = X @ Wl,  R = X @ Wr       out[128rows x 128cols] each, K=128
// 512 threads = 16 warps: p = wid/8 (matrix), wm = wid%4 (M/32), wn = (wid%8)/4 (N/64)
// smem: A hi/lo [128][136] bf16  +  B (2 mats x hi/lo) [128][136] bf16
// ---------------------------------------------------------------------------
#define ASTRIDE 136
#define ATILE (128 * ASTRIDE * 2)          // 34816 bytes
#define B_BASE (2 * ATILE)
#define GEMM_SMEM (6 * ATILE)              // 208896 bytes

__global__ void __launch_bounds__(512, 1)
gemm_dual_kernel(const float* __restrict__ X, int matl, int matr,
                 float* __restrict__ outP, float* __restrict__ outR, int n) {
    extern __shared__ char smem[];
    uint32_t sb = smem_to_u32(smem);
    int tid = threadIdx.x;
    int wid = tid >> 5;
    int lane = tid & 31;
    int rowbase = blockIdx.x * 128;

    // ---- A: fp32 -> bf16 hi/lo into padded smem. thread = (row, 32k-quarter)
    {
        int row = tid >> 2;
        int q = tid & 3;
        bool valid = (rowbase + row) < n;
        const float4* Xr = (const float4*)(X + (size_t)(rowbase + row) * D + q * 32);
        uint16_t* hb = (uint16_t*)smem + row * ASTRIDE + q * 32;
        uint16_t* lb = hb + 128 * ASTRIDE;
        float4 z = make_float4(0.f, 0.f, 0.f, 0.f);
#pragma unroll
        for (int i = 0; i < 8; i++) {
            float4 v = valid ? Xr[i] : z;
            uint32_t hp0 = pack_bf(v.x, v.y);
            uint32_t hp1 = pack_bf(v.z, v.w);
            float h0 = __uint_as_float(hp0 << 16);
            float h1 = __uint_as_float(hp0 & 0xFFFF0000u);
            float h2 = __uint_as_float(hp1 << 16);
            float h3 = __uint_as_float(hp1 & 0xFFFF0000u);
            uint32_t lp0 = pack_bf(v.x - h0, v.y - h1);
            uint32_t lp1 = pack_bf(v.z - h2, v.w - h3);
            *(uint2*)(hb + i * 4) = make_uint2(hp0, hp1);
            *(uint2*)(lb + i * 4) = make_uint2(lp0, lp1);
        }
    }
    // ---- B: copy preconverted weights: [matl hi, matl lo, matr hi, matr lo]
    {
        const uint4* sl = (const uint4*)(g_Wb + (size_t)matl * 2 * WMAT);
        const uint4* sr = (const uint4*)(g_Wb + (size_t)matr * 2 * WMAT);
        uint4* db = (uint4*)(smem + B_BASE);
        const int Q = 2 * WMAT / 8;   // uint4 count per matrix (hi+lo) = 4352
        for (int i = tid; i < 2 * Q; i += 512)
            db[i] = (i < Q) ? sl[i] : sr[i - Q];
    }
    __syncthreads();

    int p = wid >> 3;          // 0 -> P (matl), 1 -> R (matr)
    int wm = wid & 3;          // M chunk (32 rows)
    int wn = (wid >> 2) & 1;   // N chunk (64 cols)

    uint32_t As = sb;                                   // hi; lo at +ATILE
    uint32_t Bs = sb + B_BASE + p * 2 * ATILE;          // hi; lo at +ATILE

    // lane-dependent ldmatrix offsets (elements)
    int aoff = ((lane & 7) + ((lane >> 3) & 1) * 8) * ASTRIDE + (lane >> 4) * 8;
    int boff = ((lane & 7) + (lane >> 4) * 8) * ASTRIDE + ((lane >> 3) & 1) * 8;

    float acc[2][8][4];
#pragma unroll
    for (int mi = 0; mi < 2; mi++)
#pragma unroll
        for (int ni = 0; ni < 8; ni++)
#pragma unroll
            for (int c = 0; c < 4; c++) acc[mi][ni][c] = 0.f;

#pragma unroll
    for (int prod = 0; prod < 3; prod++) {
        uint32_t Ab = As + ((prod == 2) ? ATILE : 0);   // Alo only in product 2
        uint32_t Bb = Bs + ((prod == 1) ? ATILE : 0);   // Blo only in product 1
#pragma unroll
        for (int ks = 0; ks < 8; ks++) {
            int k = ks * 16;
            uint32_t a[2][4];
#pragma unroll
            for (int mi = 0; mi < 2; mi++) {
                uint32_t addr = Ab + ((wm * 32 + mi * 16) * ASTRIDE + k + aoff) * 2;
                ldsm_x4(addr, a[mi][0], a[mi][1], a[mi][2], a[mi][3]);
            }
#pragma unroll
            for (int nb = 0; nb < 4; nb++) {            // 2 n8-blocks per ldmatrix
                uint32_t addr = Bb + ((wn * 64 + nb * 16) * ASTRIDE + k + boff) * 2;
                uint32_t b0, b1, b2, b3;
                ldsm_x4(addr, b0, b1, b2, b3);
#pragma unroll
                for (int mi = 0; mi < 2; mi++) {
                    mma16816(acc[mi][nb * 2], a[mi][0], a[mi][1], a[mi][2], a[mi][3], b0, b1);
                    mma16816(acc[mi][nb * 2 + 1], a[mi][0], a[mi][1], a[mi][2], a[mi][3], b2, b3);
                }
            }
        }
    }

    // ---- epilogue: direct global stores
    float* out = p ? outR : outP;
#pragma unroll
    for (int mi = 0; mi < 2; mi++) {
        int r0 = rowbase + wm * 32 + mi * 16 + (lane >> 2);
        int r1 = r0 + 8;
#pragma unroll
        for (int ni = 0; ni < 8; ni++) {
            int col = wn * 64 + ni * 8 + (lane & 3) * 2;
            if (r0 < n) *(float2*)(out + (size_t)r0 * D + col) = make_float2(acc[mi][ni][0], acc[mi][ni][1]);
            if (r1 < n) *(float2*)(out + (size_t)r1 * D + col) = make_float2(acc[mi][ni][2], acc[mi][ni][3]);
        }
    }
}

// ---------------------------------------------------------------------------
// gather: 4 warps per node, each warp owns 32 features
// out[v] = mean_nbr(P) + R[v] + b   (+ReLU)
// ---------------------------------------------------------------------------
template <int RELU>
__global__ void gather_kernel(const float* __restrict__ P,
                              const float* __restrict__ R,
                              const float* __restrict__ bias,
                              float* __restrict__ out, int n) {
    int gw = (blockIdx.x * blockDim.x + threadIdx.x) >> 5;
    int lane = threadIdx.x & 31;
    int w = gw >> 2;
    int q = gw & 3;
    if (w >= n) return;
    int p0 = g_ptr[w], p1 = g_ptr[w + 1];
    int col = q * 32 + lane;
    const float* Pc = P + col;
    float a0 = 0.f, a1 = 0.f, a2 = 0.f, a3 = 0.f;
    int j = p0;
    for (; j + 4 <= p1; j += 4) {
        int s0 = g_nbr[j], s1 = g_nbr[j + 1], s2 = g_nbr[j + 2], s3 = g_nbr[j + 3];
        a0 += Pc[(size_t)s0 * D];
        a1 += Pc[(size_t)s1 * D];
        a2 += Pc[(size_t)s2 * D];
        a3 += Pc[(size_t)s3 * D];
    }
    for (; j < p1; j++) a0 += Pc[(size_t)g_nbr[j] * D];
    float acc = (a0 + a1) + (a2 + a3);
    float inv = 1.0f / fmaxf((float)(p1 - p0), 1.0f);
    float res = acc * inv + R[(size_t)w * D + col] + bias[col];
    if (RELU) res = fmaxf(res, 0.0f);
    out[(size_t)w * D + col] = res;
}

// ---------------------------------------------------------------------------
extern "C" void kernel_launch(void* const* d_in, const int* in_sizes, int n_in,
                              void* d_out, int out_size) {
    const float* x   = (const float*)d_in[0];
    const void*  ei  = d_in[1];
    const float* W1l = (const float*)d_in[2];
    const float* b1  = (const float*)d_in[3];
    const float* W1r = (const float*)d_in[4];
    const float* W2l = (const float*)d_in[5];
    const float* b2  = (const float*)d_in[6];
    const float* W2r = (const float*)d_in[7];
    float* out = (float*)d_out;

    int n = in_sizes[0] / D;
    int E = in_sizes[1] / 2;

    float *P, *R, *H;
    cudaGetSymbolAddress((void**)&P, g_P);
    cudaGetSymbolAddress((void**)&R, g_R);
    cudaGetSymbolAddress((void**)&H, g_H);

    cudaFuncSetAttribute(gemm_dual_kernel, cudaFuncAttributeMaxDynamicSharedMemorySize, GEMM_SMEM);

    int G  = (n + 127) / 128;
    int NB = (n + 511) / 512;
    int gatherBlocks = (n * 128 + 255) / 256;

    // CSR build + weight conversion (shared by both layers)
    detect_kernel<<<1, 32>>>((const int*)ei, E);
    zero_cnt_kernel<<<256, 256>>>(n);
    count_kernel<<<(E + 255) / 256, 256>>>(ei, E);
    scanA_kernel<<<NB, 512>>>(n);
    scanB_kernel<<<1, 256>>>(NB);
    scanC_kernel<<<(n + 255) / 256, 256>>>(n, E);
    fill_kernel<<<(E + 255) / 256, 256>>>(ei, E);
    wconv_kernel<<<4, 256>>>(W1l, W1r, W2l, W2r);

    // layer 1
    gemm_dual_kernel<<<G, 512, GEMM_SMEM>>>(x, 0, 1, P, R, n);
    gather_kernel<1><<<gatherBlocks, 256>>>(P, R, b1, H, n);

    // layer 2
    gemm_dual_kernel<<<G, 512, GEMM_SMEM>>>(H, 2, 3, P, R, n);
    gather_kernel<0><<<gatherBlocks, 256>>>(P, R, b2, out, n);
}